// round 14
// baseline (speedup 1.0000x reference)
#include <cuda_runtime.h>
#include <math.h>

#define S7 7
#define NPTS 49              // 7*7 sample points per ROI
#define NCH 256              // channels
#define NGROUPS 8            // channel groups per block
#define CPG (NCH / NGROUPS)  // 32 channels per group
#define THREADS (NGROUPS * NPTS)  // 392

// R14: held stable (fourteen GPU-acquisition timeouts; zero measurements yet).
// Candidate frozen; desk-side verification exhausted in prior rounds.

__global__ __launch_bounds__(THREADS)
void rroi_align_kernel(const float* __restrict__ f0, const float* __restrict__ f1,
                       const float* __restrict__ f2, const float* __restrict__ f3,
                       const float* __restrict__ rois, const int* __restrict__ levels,
                       float* __restrict__ out, int N)
{
    const int rid = blockIdx.x;        // b*N + n
    const int b   = rid / N;
    const int tid = threadIdx.x;
    const int g   = tid / NPTS;        // channel group 0..7
    const int p   = tid - g * NPTS;    // sample point 0..48

    // front-batch the tiny prologue loads (levels + 3x float2 ROI row).
    // ROI row is 24B -> always 8-aligned, never 16-aligned for odd rid,
    // so float2 (LDG.64) is the widest legal access.
    const int lvl = __ldg(levels + rid);
    const float2 r01 = *(const float2*)(rois + (size_t)rid * 6);
    const float2 r23 = *(const float2*)(rois + (size_t)rid * 6 + 2);
    const float2 r45 = *(const float2*)(rois + (size_t)rid * 6 + 4);

    const float* feat; int H, W; float scale; bool valid = true;
    switch (lvl) {
        case 0: feat = f0; H = 256; W = 256; scale = 0.25f;    break;
        case 1: feat = f1; H = 128; W = 128; scale = 0.125f;   break;
        case 2: feat = f2; H = 64;  W = 64;  scale = 0.0625f;  break;
        case 3: feat = f3; H = 32;  W = 32;  scale = 0.03125f; break;
        default: feat = f3; H = 32; W = 32; scale = 0.03125f; valid = false; break;
    }

    float* o = out + (size_t)rid * (NCH * NPTS);
    if (!valid) {
        // levels are in [0,4) by construction; kept because d_out is poisoned
        for (int e = tid; e < NCH * NPTS; e += THREADS) o[e] = 0.0f;
        return;
    }

    // ---- per-thread ROI math (registers only; identical op order to reference) ----
    const float x  = r01.x, y  = r01.y;
    const float w  = r23.x, h  = r23.y;
    const float a  = r45.x, bb = r45.y;

    const float v1x = x + a,        v1y = y + 0.5f * h;
    const float v2x = x + 0.5f * w, v2y = y + bb;
    const float v3x = x - a,        v3y = y - 0.5f * h;
    const float v4x = x - 0.5f * w, v4y = y - bb;

    const float d1 = sqrtf((v3x - v1x) * (v3x - v1x) + (v3y - v1y) * (v3y - v1y));
    const float d2 = sqrtf((v4x - v2x) * (v4x - v2x) + (v4y - v2y) * (v4y - v2y));
    const float eps = 1e-6f;

    float V0x, V0y, V1x, V1y, V2x, V2y;
    if (d1 > d2) {
        const float sA = d1 / (d2 + eps) - 1.0f;     // stretch v2/v4
        V0x = v1x;                   V0y = v1y;
        V1x = v2x + sA * (0.5f * w); V1y = v2y + sA * bb;
        V2x = v3x;                   V2y = v3y;
    } else {
        const float sB = d2 / (d1 + eps) - 1.0f;     // stretch v1/v3
        V0x = v1x + sB * a;          V0y = v1y + sB * (0.5f * h);
        V1x = v2x;                   V1y = v2y;
        V2x = v3x - sB * a;          V2y = v3y - sB * (0.5f * h);
    }

    const float h_rect = sqrtf((V1x - V0x) * (V1x - V0x) + (V1y - V0y) * (V1y - V0y));
    const float w_rect = sqrtf((V2x - V1x) * (V2x - V1x) + (V2y - V1y) * (V2y - V1y));
    float theta = atan2f(V1y - V2y, V1x - V2x);
    const float HPI = 1.5707963267948966f;
    theta = fminf(fmaxf(theta, -HPI), HPI);

    const float ct = cosf(theta);
    const float st = sinf(theta);

    // ---- this thread's 7x7 grid point ----
    const int row = p / S7;
    const int col = p - row * S7;
    const float tc = (float)col / 6.0f - 0.5f;   // linspace(-0.5, 0.5, 7)
    const float tr = (float)row / 6.0f - 0.5f;

    const float gx = w_rect * scale * tc;        // columns vary x
    const float gy = h_rect * scale * tr;        // rows vary y
    const float rx =  gx * ct + gy * st + x * scale;
    const float ry = -gx * st + gy * ct + y * scale;

    // faithful double-scaling + normalize + unmap chain
    const float gxn = rx * scale / (float)(W - 1) * 2.0f - 1.0f;
    const float gyn = ry * scale / (float)(H - 1) * 2.0f - 1.0f;
    const float px = ((gxn + 1.0f) * (float)W - 1.0f) * 0.5f;
    const float py = ((gyn + 1.0f) * (float)H - 1.0f) * 0.5f;

    // ---- bilinear corner indices + weights (border clamp on indices only) ----
    const float x0f = floorf(px);
    const float y0f = floorf(py);
    const float wx = px - x0f;
    const float wy = py - y0f;

    int ix0 = (int)x0f; ix0 = ix0 < 0 ? 0 : (ix0 > W - 1 ? W - 1 : ix0);
    int ix1 = ix0 + 1;  ix1 = ix1 > W - 1 ? W - 1 : ix1;
    int iy0 = (int)y0f; iy0 = iy0 < 0 ? 0 : (iy0 > H - 1 ? H - 1 : iy0);
    int iy1 = iy0 + 1;  iy1 = iy1 > H - 1 ? H - 1 : iy1;

    const int i00 = iy0 * W + ix0;
    const int i01 = iy0 * W + ix1;
    const int i10 = iy1 * W + ix0;
    const int i11 = iy1 * W + ix1;
    const float w00 = (1.0f - wx) * (1.0f - wy);
    const float w01 = wx * (1.0f - wy);
    const float w10 = (1.0f - wx) * wy;
    const float w11 = wx * wy;

    // ---- channel loop: 32 channels for this group, all state in registers ----
    // unroll 8 => 32 independent LDGs in flight (per-warp cap ~55) to hide
    // L2-hit latency on the scattered level-0 gathers.
    const int HW = H * W;
    const int c0 = g * CPG;
    const float* fc = feat + ((size_t)b * NCH + c0) * HW;
    float* op = o + c0 * NPTS + p;

    #pragma unroll 8
    for (int cc = 0; cc < CPG; ++cc) {
        const float v = __ldg(fc + i00) * w00
                      + __ldg(fc + i01) * w01
                      + __ldg(fc + i10) * w10
                      + __ldg(fc + i11) * w11;
        *op = v;
        fc += HW;
        op += NPTS;
    }
}

extern "C" void kernel_launch(void* const* d_in, const int* in_sizes, int n_in,
                              void* d_out, int out_size)
{
    const float* f0     = (const float*)d_in[0];
    const float* f1     = (const float*)d_in[1];
    const float* f2     = (const float*)d_in[2];
    const float* f3     = (const float*)d_in[3];
    const float* rois   = (const float*)d_in[4];
    const int*   levels = (const int*)  d_in[5];
    float*       out    = (float*)d_out;

    // derive B, N from sizes: f0 is [B,256,256,256]; levels is [B,N]
    const int B  = in_sizes[0] / (NCH * 256 * 256);
    const int BN = in_sizes[5];
    const int N  = BN / B;

    rroi_align_kernel<<<BN, THREADS>>>(f0, f1, f2, f3, rois, levels, out, N);
}